// round 4
// baseline (speedup 1.0000x reference)
#include <cuda_runtime.h>
#include <math.h>

#define BATCH   1024
#define DIM     512
#define NCLS    100000
#define SCALE   64.0f
#define MARGIN  0.5f
#define PI_F    3.14159265358979323846f

#define BM 128
#define BN 128
#define BK 16
#define NCHUNK ((NCLS + BN - 1) / BN)   // 782

// Scratch (device globals; no allocation allowed)
__device__ float g_inv_e[BATCH];
__device__ float g_inv_w[NCLS];
__device__ float g_pmax[BATCH * NCHUNK];
__device__ float g_psum[BATCH * NCHUNK];
__device__ float g_told[BATCH];      // original target logit * SCALE
__device__ float g_tnew[BATCH];      // margined target logit * SCALE
__device__ float g_rowloss[BATCH];
__device__ int   g_lbl64;            // 1 if labels are int64, 0 if int32

// ---------------------------------------------------------------------------
// Kernel 0: detect label dtype. Reads exactly the first 4096 bytes (in-bounds
// for both int32[1024] and int64[1024]). If all 512 int64 interpretations are
// valid class ids, the buffer is int64; otherwise it is int32 (pairs of int32
// labels combine to values >= 2^32 with overwhelming probability).
// ---------------------------------------------------------------------------
__global__ void detect_kernel(const void* __restrict__ lbl) {
    __shared__ int ok;
    if (threadIdx.x == 0) ok = 1;
    __syncthreads();
    long long v = ((const long long*)lbl)[threadIdx.x];   // 512 threads
    if (v < 0 || v >= (long long)NCLS) atomicAnd(&ok, 0);
    __syncthreads();
    if (threadIdx.x == 0) g_lbl64 = ok;
}

// ---------------------------------------------------------------------------
// Kernel 1: inverse L2 norms for embeddings (rows 0..B-1) and weight rows
// (rows B..B+C-1). One warp per row, float4 loads, shuffle reduce.
// ---------------------------------------------------------------------------
__global__ void norm_kernel(const float* __restrict__ emb,
                            const float* __restrict__ wgt) {
    int row = blockIdx.x * 8 + (threadIdx.x >> 5);
    int lane = threadIdx.x & 31;
    const float* src;
    float* dst;
    if (row < BATCH) {
        src = emb + (size_t)row * DIM;
        dst = &g_inv_e[row];
    } else {
        int r = row - BATCH;
        if (r >= NCLS) return;
        src = wgt + (size_t)r * DIM;
        dst = &g_inv_w[r];
    }
    const float4* p = (const float4*)src;
    float s = 0.f;
#pragma unroll
    for (int i = 0; i < 4; i++) {
        float4 v = p[lane + i * 32];
        s = fmaf(v.x, v.x, s);
        s = fmaf(v.y, v.y, s);
        s = fmaf(v.z, v.z, s);
        s = fmaf(v.w, v.w, s);
    }
#pragma unroll
    for (int o = 16; o; o >>= 1) s += __shfl_xor_sync(0xFFFFFFFFu, s, o);
    if (lane == 0) *dst = rsqrtf(s);
}

// ---------------------------------------------------------------------------
// Kernel 2: fused GEMM (128x128x512 tiles) + per-chunk online-softmax
// partials over ORIGINAL scaled logits. No label logic here.
// ---------------------------------------------------------------------------
__global__ __launch_bounds__(256, 2)
void gemm_partial_kernel(const float* __restrict__ A,       // embeddings [B,D]
                         const float* __restrict__ W) {     // weight [C,D]
    __shared__ float As[BK][BM + 4];
    __shared__ float Bs[BK][BN + 4];

    const int chunk   = blockIdx.x;
    const int rowBase = blockIdx.y * BM;
    const int colBase = chunk * BN;
    const int tid = threadIdx.x;
    const int tx = tid & 15;
    const int ty = tid >> 4;

    float acc[8][8];
#pragma unroll
    for (int i = 0; i < 8; i++)
#pragma unroll
        for (int j = 0; j < 8; j++) acc[i][j] = 0.f;

    for (int kt = 0; kt < DIM / BK; kt++) {
        const int kBase = kt * BK;
#pragma unroll
        for (int l = 0; l < 2; l++) {
            int idx = tid + l * 256;        // 0..511
            int r   = idx >> 2;             // 0..127
            int kg  = (idx & 3) << 2;       // 0,4,8,12
            float4 av = *(const float4*)(A + (size_t)(rowBase + r) * DIM + kBase + kg);
            As[kg + 0][r] = av.x;
            As[kg + 1][r] = av.y;
            As[kg + 2][r] = av.z;
            As[kg + 3][r] = av.w;
            int c = colBase + r;
            float4 bv = make_float4(0.f, 0.f, 0.f, 0.f);
            if (c < NCLS)
                bv = *(const float4*)(W + (size_t)c * DIM + kBase + kg);
            Bs[kg + 0][r] = bv.x;
            Bs[kg + 1][r] = bv.y;
            Bs[kg + 2][r] = bv.z;
            Bs[kg + 3][r] = bv.w;
        }
        __syncthreads();
#pragma unroll
        for (int k = 0; k < BK; k++) {
            float4 a0 = *(const float4*)&As[k][ty * 4];
            float4 a1 = *(const float4*)&As[k][64 + ty * 4];
            float4 b0 = *(const float4*)&Bs[k][tx * 4];
            float4 b1 = *(const float4*)&Bs[k][64 + tx * 4];
            float ar[8] = {a0.x, a0.y, a0.z, a0.w, a1.x, a1.y, a1.z, a1.w};
            float br[8] = {b0.x, b0.y, b0.z, b0.w, b1.x, b1.y, b1.z, b1.w};
#pragma unroll
            for (int i = 0; i < 8; i++)
#pragma unroll
                for (int j = 0; j < 8; j++)
                    acc[i][j] = fmaf(ar[i], br[j], acc[i][j]);
        }
        __syncthreads();
    }

    // ---- Epilogue: cos -> clip -> scale -> per-row chunk max/sumexp ----
    int cols[8];
    float invw[8];
#pragma unroll
    for (int j = 0; j < 8; j++) {
        int c = colBase + ((j < 4) ? (tx * 4 + j) : (64 + tx * 4 + j - 4));
        cols[j] = c;
        invw[j] = (c < NCLS) ? g_inv_w[c] : 0.f;
    }

#pragma unroll
    for (int i = 0; i < 8; i++) {
        int r = rowBase + ((i < 4) ? (ty * 4 + i) : (64 + ty * 4 + i - 4));
        float invE = g_inv_e[r];

        float vals[8];
        float m = -1e30f;
#pragma unroll
        for (int j = 0; j < 8; j++) {
            float v;
            if (cols[j] < NCLS) {
                v = acc[i][j] * invE * invw[j];
                v = fminf(1.f, fmaxf(-1.f, v));
                v *= SCALE;
            } else {
                v = -1e30f;   // excluded from softmax
            }
            vals[j] = v;
            m = fmaxf(m, v);
        }
        // reduce max across the 16 tx lanes (contiguous within half-warp)
#pragma unroll
        for (int o = 8; o; o >>= 1) m = fmaxf(m, __shfl_xor_sync(0xFFFFFFFFu, m, o));
        float s = 0.f;
#pragma unroll
        for (int j = 0; j < 8; j++) s += __expf(vals[j] - m);
#pragma unroll
        for (int o = 8; o; o >>= 1) s += __shfl_xor_sync(0xFFFFFFFFu, s, o);

        if (tx == 0) {
            g_pmax[(size_t)r * NCHUNK + chunk] = m;
            g_psum[(size_t)r * NCHUNK + chunk] = s;
        }
    }
}

// ---------------------------------------------------------------------------
// Kernel 3: per-row target logit. One warp per row. Dot(emb[row], W[label]),
// normalize, clip, store original*S and margined*S. Label dtype from g_lbl64.
// ---------------------------------------------------------------------------
__global__ void target_kernel(const float* __restrict__ emb,
                              const float* __restrict__ wgt,
                              const void* __restrict__ lbl) {
    int row  = blockIdx.x * 8 + (threadIdx.x >> 5);
    int lane = threadIdx.x & 31;
    if (row >= BATCH) return;

    long long lab = g_lbl64 ? ((const long long*)lbl)[row]
                            : (long long)((const int*)lbl)[row];

    const float4* e4 = (const float4*)(emb + (size_t)row * DIM);
    const float4* w4 = (const float4*)(wgt + (size_t)lab * DIM);
    float s = 0.f;
#pragma unroll
    for (int i = 0; i < 4; i++) {
        float4 a = e4[lane + i * 32];
        float4 b = w4[lane + i * 32];
        s = fmaf(a.x, b.x, s);
        s = fmaf(a.y, b.y, s);
        s = fmaf(a.z, b.z, s);
        s = fmaf(a.w, b.w, s);
    }
#pragma unroll
    for (int o = 16; o; o >>= 1) s += __shfl_xor_sync(0xFFFFFFFFu, s, o);

    if (lane == 0) {
        float t = s * g_inv_e[row] * g_inv_w[lab];
        t = fminf(1.f, fmaxf(-1.f, t));
        float th = acosf(t);
        float tn = cosf(fminf(th + MARGIN, PI_F));
        g_told[row] = t  * SCALE;
        g_tnew[row] = tn * SCALE;
    }
}

// ---------------------------------------------------------------------------
// Kernel 4: per-row online logsumexp merge over NCHUNK partials; one warp/row.
// Then substitute the target term (remove original, add margined):
//   s' = s + exp(t_new - m) - exp(t_old - m)   (t_old's term is inside s)
//   row_loss = (m + log s') - t_new
// ---------------------------------------------------------------------------
__global__ void lse_kernel() {
    int row  = blockIdx.x * 8 + (threadIdx.x >> 5);
    int lane = threadIdx.x & 31;
    if (row >= BATCH) return;

    float m = -1e30f, s = 0.f;
    const float* pm_base = &g_pmax[(size_t)row * NCHUNK];
    const float* ps_base = &g_psum[(size_t)row * NCHUNK];
    for (int ch = lane; ch < NCHUNK; ch += 32) {
        float pm = pm_base[ch];
        float ps = ps_base[ch];
        if (pm > m) {
            s = s * __expf(m - pm) + ps;
            m = pm;
        } else {
            s += ps * __expf(pm - m);
        }
    }
#pragma unroll
    for (int o = 16; o; o >>= 1) {
        float om = __shfl_xor_sync(0xFFFFFFFFu, m, o);
        float os = __shfl_xor_sync(0xFFFFFFFFu, s, o);
        if (om > m) {
            s = s * __expf(m - om) + os;
            m = om;
        } else {
            s += os * __expf(om - m);
        }
    }
    if (lane == 0) {
        float tn = g_tnew[row];
        float to = g_told[row];
        float s2 = s + __expf(tn - m) - __expf(to - m);
        s2 = fmaxf(s2, 1e-30f);
        g_rowloss[row] = m + logf(s2) - tn;
    }
}

// ---------------------------------------------------------------------------
// Kernel 5: mean over rows -> d_out[0]
// ---------------------------------------------------------------------------
__global__ void final_kernel(float* __restrict__ out) {
    __shared__ float sh[256];
    float s = 0.f;
    for (int r = threadIdx.x; r < BATCH; r += 256) s += g_rowloss[r];
    sh[threadIdx.x] = s;
    __syncthreads();
    for (int o = 128; o; o >>= 1) {
        if (threadIdx.x < o) sh[threadIdx.x] += sh[threadIdx.x + o];
        __syncthreads();
    }
    if (threadIdx.x == 0) out[0] = sh[0] / (float)BATCH;
}

// ---------------------------------------------------------------------------
extern "C" void kernel_launch(void* const* d_in, const int* in_sizes, int n_in,
                              void* d_out, int out_size) {
    (void)in_sizes; (void)n_in; (void)out_size;
    const float* emb = (const float*)d_in[0];
    const float* wgt = (const float*)d_in[1];
    const void*  lbl = d_in[2];
    float* out       = (float*)d_out;

    // 0) label dtype detection (reads exactly 4KB, safe for int32 or int64)
    detect_kernel<<<1, 512>>>(lbl);

    // 1) norms (embeddings + weight rows), 8 warps/block
    int totalRows = BATCH + NCLS;
    norm_kernel<<<(totalRows + 7) / 8, 256>>>(emb, wgt);

    // 2) fused GEMM + chunk softmax partials (original logits)
    dim3 grid(NCHUNK, BATCH / BM);
    gemm_partial_kernel<<<grid, 256>>>(emb, wgt);

    // 3) per-row target logit (original + margined)
    target_kernel<<<BATCH / 8, 256>>>(emb, wgt, lbl);

    // 4) per-row LSE merge + target substitution
    lse_kernel<<<BATCH / 8, 256>>>();

    // 5) mean loss
    final_kernel<<<1, 256>>>(out);
}

// round 7
// speedup vs baseline: 4.8743x; 4.8743x over previous
#include <cuda_runtime.h>
#include <cuda_bf16.h>
#include <math.h>
#include <stdint.h>

#define BATCH    1024
#define DIM      512
#define NCLS     100000
#define NCLS_PAD 100096              // 782 * 128
#define SCALE    64.0f
#define MARGIN   0.5f
#define PI_F     3.14159265358979323846f

#define BM  128
#define BN  128
#define KT  64                        // K per stage
#define NSTAGE (DIM / KT)             // 8
#define NCHUNK (NCLS_PAD / BN)        // 782
#define SA  72                        // padded SMEM row stride (bf16 elems)

#define TILE_BYTES (128 * SA * 2)     // 18432
#define SM_A0 0
#define SM_B0 (TILE_BYTES)
#define SM_A1 (2 * TILE_BYTES)
#define SM_B1 (3 * TILE_BYTES)
#define SM_TOTAL (4 * TILE_BYTES)     // 73728

// ---------------- device scratch (no allocation allowed) -------------------
__device__ __nv_bfloat16 g_ebf[BATCH * DIM];       // normalized embeddings
__device__ __nv_bfloat16 g_wbf[NCLS_PAD * DIM];    // normalized weights (padded zero)
__device__ float g_inv_e[BATCH];
__device__ float g_inv_w[NCLS];
__device__ float g_pmax[BATCH * NCHUNK];
__device__ float g_psum[BATCH * NCHUNK];
__device__ float g_told[BATCH];
__device__ float g_tnew[BATCH];
__device__ float g_rowloss[BATCH];
__device__ int   g_lbl64;

// ---------------- PTX helpers (compute_103-safe: sm_80-era MMA) -------------
__device__ __forceinline__ uint32_t smem_u32(const void* p) {
    uint32_t a;
    asm("{ .reg .u64 t; cvta.to.shared.u64 t, %1; cvt.u32.u64 %0, t; }" : "=r"(a) : "l"(p));
    return a;
}

__device__ __forceinline__ void ldsm_x4(uint32_t& r0, uint32_t& r1,
                                        uint32_t& r2, uint32_t& r3, uint32_t addr) {
    asm volatile("ldmatrix.sync.aligned.m8n8.x4.shared.b16 {%0,%1,%2,%3}, [%4];"
                 : "=r"(r0), "=r"(r1), "=r"(r2), "=r"(r3) : "r"(addr));
}

__device__ __forceinline__ void mma_bf16(float* c,
                                         uint32_t a0, uint32_t a1, uint32_t a2, uint32_t a3,
                                         uint32_t b0, uint32_t b1) {
    asm volatile(
        "mma.sync.aligned.m16n8k16.row.col.f32.bf16.bf16.f32 "
        "{%0,%1,%2,%3}, {%4,%5,%6,%7}, {%8,%9}, {%0,%1,%2,%3};"
        : "+f"(c[0]), "+f"(c[1]), "+f"(c[2]), "+f"(c[3])
        : "r"(a0), "r"(a1), "r"(a2), "r"(a3), "r"(b0), "r"(b1));
}

// ---------------------------------------------------------------------------
// Kernel 0: detect label dtype (reads exactly first 4KB; safe for i32/i64).
// ---------------------------------------------------------------------------
__global__ void detect_kernel(const void* __restrict__ lbl) {
    __shared__ int ok;
    if (threadIdx.x == 0) ok = 1;
    __syncthreads();
    long long v = ((const long long*)lbl)[threadIdx.x];   // 512 threads
    if (v < 0 || v >= (long long)NCLS) atomicAnd(&ok, 0);
    __syncthreads();
    if (threadIdx.x == 0) g_lbl64 = ok;
}

// ---------------------------------------------------------------------------
// Kernel 1: fused norm + bf16 convert. One warp per row.
// ---------------------------------------------------------------------------
__global__ void prep_kernel(const float* __restrict__ emb,
                            const float* __restrict__ wgt) {
    int row  = blockIdx.x * 8 + (threadIdx.x >> 5);
    int lane = threadIdx.x & 31;

    const float* src;
    __nv_bfloat16* dstRow;
    float* invDst;
    if (row < BATCH) {
        src = emb + (size_t)row * DIM;
        dstRow = &g_ebf[(size_t)row * DIM];
        invDst = &g_inv_e[row];
    } else {
        int r = row - BATCH;
        if (r >= NCLS_PAD) return;
        dstRow = &g_wbf[(size_t)r * DIM];
        if (r >= NCLS) {   // pad rows: zero
            uint2 z = make_uint2(0u, 0u);
#pragma unroll
            for (int i = 0; i < 4; i++) ((uint2*)dstRow)[lane + i * 32] = z;
            return;
        }
        src = wgt + (size_t)r * DIM;
        invDst = &g_inv_w[r];
    }

    const float4* p = (const float4*)src;
    float4 v[4];
    float s = 0.f;
#pragma unroll
    for (int i = 0; i < 4; i++) {
        v[i] = p[lane + i * 32];
        s = fmaf(v[i].x, v[i].x, s);
        s = fmaf(v[i].y, v[i].y, s);
        s = fmaf(v[i].z, v[i].z, s);
        s = fmaf(v[i].w, v[i].w, s);
    }
#pragma unroll
    for (int o = 16; o; o >>= 1) s += __shfl_xor_sync(0xFFFFFFFFu, s, o);
    float inv = rsqrtf(s);
    if (lane == 0) *invDst = inv;

#pragma unroll
    for (int i = 0; i < 4; i++) {
        __nv_bfloat162 lo = __floats2bfloat162_rn(v[i].x * inv, v[i].y * inv);
        __nv_bfloat162 hi = __floats2bfloat162_rn(v[i].z * inv, v[i].w * inv);
        uint2 pk;
        pk.x = *(uint32_t*)&lo;
        pk.y = *(uint32_t*)&hi;
        ((uint2*)dstRow)[lane + i * 32] = pk;
    }
}

// ---------------------------------------------------------------------------
// Kernel 2: bf16 mma.sync GEMM 128x128x512 + per-chunk softmax partials.
// 8 warps (2 m x 4 n), warp tile 64x32, m16n8k16 fragments, KT=64 double buf.
// ---------------------------------------------------------------------------
__device__ __forceinline__ void load_stage(char* smem, int aoff, int boff,
                                           int rowBase, int colBase, int kBase, int tid) {
#pragma unroll
    for (int t = 0; t < 4; t++) {
        int idx = tid + t * 256;          // 0..1023
        int r = idx >> 3;                  // 0..127
        int c = (idx & 7) * 8;             // 0..56
        uint4 va = *(const uint4*)&g_ebf[(size_t)(rowBase + r) * DIM + kBase + c];
        *(uint4*)(smem + aoff + (r * SA + c) * 2) = va;
        uint4 vb = *(const uint4*)&g_wbf[(size_t)(colBase + r) * DIM + kBase + c];
        *(uint4*)(smem + boff + (r * SA + c) * 2) = vb;
    }
}

__global__ __launch_bounds__(256, 2)
void gemm_mma_kernel() {
    extern __shared__ __align__(16) char smem[];
    const uint32_t smem_base = smem_u32(smem);
    const int tid  = threadIdx.x;
    const int wid  = tid >> 5;
    const int lane = tid & 31;
    const int wr   = wid >> 2;           // 0..1  (m)
    const int wc   = wid & 3;            // 0..3  (n)
    const int chunk   = blockIdx.x;
    const int rowBase = blockIdx.y * BM;
    const int colBase = chunk * BN;

    // per-lane ldmatrix row/col components
    const int r_in = lane & 7;
    const int a_row_base = wr * 64 + ((lane >> 3) & 1) * 8 + r_in;
    const int a_col_off  = (lane >> 4) * 8;
    const int b_row_base = wc * 32 + (lane >> 4) * 8 + r_in;
    const int b_col_off  = ((lane >> 3) & 1) * 8;

    float acc[4][4][4];
#pragma unroll
    for (int i = 0; i < 4; i++)
#pragma unroll
        for (int j = 0; j < 4; j++)
#pragma unroll
            for (int k = 0; k < 4; k++) acc[i][j][k] = 0.f;

    load_stage(smem, SM_A0, SM_B0, rowBase, colBase, 0, tid);
    __syncthreads();

    const int aoffs[2] = {SM_A0, SM_A1};
    const int boffs[2] = {SM_B0, SM_B1};

#pragma unroll
    for (int kt = 0; kt < NSTAGE; kt++) {
        const int buf = kt & 1;
        if (kt + 1 < NSTAGE)                 // prefetch next stage (other buffer)
            load_stage(smem, aoffs[buf ^ 1], boffs[buf ^ 1],
                       rowBase, colBase, (kt + 1) * KT, tid);

        const uint32_t aBase = smem_base + aoffs[buf];
        const uint32_t bBase = smem_base + boffs[buf];
#pragma unroll
        for (int ks = 0; ks < 4; ks++) {
            const int kb = ks * 16;
            uint32_t af[4][4];
#pragma unroll
            for (int mi = 0; mi < 4; mi++) {
                uint32_t addr = aBase + (((a_row_base + mi * 16) * SA) + kb + a_col_off) * 2;
                ldsm_x4(af[mi][0], af[mi][1], af[mi][2], af[mi][3], addr);
            }
            uint32_t bfr[4][2];
#pragma unroll
            for (int nb = 0; nb < 2; nb++) {
                uint32_t addr = bBase + (((b_row_base + nb * 16) * SA) + kb + b_col_off) * 2;
                uint32_t r0, r1, r2, r3;
                ldsm_x4(r0, r1, r2, r3, addr);
                bfr[nb * 2 + 0][0] = r0; bfr[nb * 2 + 0][1] = r1;
                bfr[nb * 2 + 1][0] = r2; bfr[nb * 2 + 1][1] = r3;
            }
#pragma unroll
            for (int mi = 0; mi < 4; mi++)
#pragma unroll
                for (int ni = 0; ni < 4; ni++)
                    mma_bf16(acc[mi][ni], af[mi][0], af[mi][1], af[mi][2], af[mi][3],
                             bfr[ni][0], bfr[ni][1]);
        }
        __syncthreads();
    }

    // ---- epilogue: clip*64, per-row (max, sumexp) over this 128-col chunk --
    const int gid = lane >> 2;
    const int tg  = lane & 3;
    float2* red = (float2*)smem;            // [128][4]

#pragma unroll
    for (int mi = 0; mi < 4; mi++) {
#pragma unroll
        for (int h = 0; h < 2; h++) {
            const int rloc = wr * 64 + mi * 16 + h * 8 + gid;
            float vv[8];
            bool  okk[8];
            float lm = -1e30f;
#pragma unroll
            for (int ni = 0; ni < 4; ni++) {
#pragma unroll
                for (int c = 0; c < 2; c++) {
                    int n = wc * 32 + ni * 8 + tg * 2 + c;
                    float v = acc[mi][ni][h * 2 + c];
                    v = fminf(1.f, fmaxf(-1.f, v)) * SCALE;
                    bool ok = (colBase + n) < NCLS;
                    vv[ni * 2 + c] = v;
                    okk[ni * 2 + c] = ok;
                    if (ok) lm = fmaxf(lm, v);
                }
            }
            float ls = 0.f;
#pragma unroll
            for (int j = 0; j < 8; j++)
                if (okk[j]) ls += __expf(vv[j] - lm);
            // merge across the 4 tg lanes (quad)
#pragma unroll
            for (int o = 1; o <= 2; o <<= 1) {
                float om = __shfl_xor_sync(0xFFFFFFFFu, lm, o);
                float os = __shfl_xor_sync(0xFFFFFFFFu, ls, o);
                float mn = fmaxf(lm, om);
                ls = ls * __expf(lm - mn) + os * __expf(om - mn);
                lm = mn;
            }
            if (tg == 0) red[rloc * 4 + wc] = make_float2(lm, ls);
        }
    }
    __syncthreads();

    if (tid < BM) {
        float m = -1e30f, s = 0.f;
#pragma unroll
        for (int w = 0; w < 4; w++) {
            float2 p = red[tid * 4 + w];
            float mn = fmaxf(m, p.x);
            s = s * __expf(m - mn) + p.y * __expf(p.x - mn);
            m = mn;
        }
        g_pmax[(size_t)(rowBase + tid) * NCHUNK + chunk] = m;
        g_psum[(size_t)(rowBase + tid) * NCHUNK + chunk] = s;
    }
}

// ---------------------------------------------------------------------------
// Kernel 3: per-row target logit (fp32-exact). One warp per row.
// ---------------------------------------------------------------------------
__global__ void target_kernel(const float* __restrict__ emb,
                              const float* __restrict__ wgt,
                              const void* __restrict__ lbl) {
    int row  = blockIdx.x * 8 + (threadIdx.x >> 5);
    int lane = threadIdx.x & 31;
    if (row >= BATCH) return;

    long long lab = g_lbl64 ? ((const long long*)lbl)[row]
                            : (long long)((const int*)lbl)[row];

    const float4* e4 = (const float4*)(emb + (size_t)row * DIM);
    const float4* w4 = (const float4*)(wgt + (size_t)lab * DIM);
    float s = 0.f;
#pragma unroll
    for (int i = 0; i < 4; i++) {
        float4 a = e4[lane + i * 32];
        float4 b = w4[lane + i * 32];
        s = fmaf(a.x, b.x, s);
        s = fmaf(a.y, b.y, s);
        s = fmaf(a.z, b.z, s);
        s = fmaf(a.w, b.w, s);
    }
#pragma unroll
    for (int o = 16; o; o >>= 1) s += __shfl_xor_sync(0xFFFFFFFFu, s, o);

    if (lane == 0) {
        float t = s * g_inv_e[row] * g_inv_w[lab];
        t = fminf(1.f, fmaxf(-1.f, t));
        float th = acosf(t);
        float tn = cosf(fminf(th + MARGIN, PI_F));
        g_told[row] = t  * SCALE;
        g_tnew[row] = tn * SCALE;
    }
}

// ---------------------------------------------------------------------------
// Kernel 4: per-row LSE merge over NCHUNK partials + target substitution.
// ---------------------------------------------------------------------------
__global__ void lse_kernel() {
    int row  = blockIdx.x * 8 + (threadIdx.x >> 5);
    int lane = threadIdx.x & 31;
    if (row >= BATCH) return;

    float m = -1e30f, s = 0.f;
    const float* pm_base = &g_pmax[(size_t)row * NCHUNK];
    const float* ps_base = &g_psum[(size_t)row * NCHUNK];
    for (int ch = lane; ch < NCHUNK; ch += 32) {
        float pm = pm_base[ch];
        float ps = ps_base[ch];
        float mn = fmaxf(m, pm);
        s = s * __expf(m - mn) + ps * __expf(pm - mn);
        m = mn;
    }
#pragma unroll
    for (int o = 16; o; o >>= 1) {
        float om = __shfl_xor_sync(0xFFFFFFFFu, m, o);
        float os = __shfl_xor_sync(0xFFFFFFFFu, s, o);
        float mn = fmaxf(m, om);
        s = s * __expf(m - mn) + os * __expf(om - mn);
        m = mn;
    }
    if (lane == 0) {
        float tn = g_tnew[row];
        float to = g_told[row];
        float s2 = s + __expf(tn - m) - __expf(to - m);
        s2 = fmaxf(s2, 1e-30f);
        g_rowloss[row] = m + logf(s2) - tn;
    }
}

// ---------------------------------------------------------------------------
// Kernel 5: mean over rows -> d_out[0]
// ---------------------------------------------------------------------------
__global__ void final_kernel(float* __restrict__ out) {
    __shared__ float sh[256];
    float s = 0.f;
    for (int r = threadIdx.x; r < BATCH; r += 256) s += g_rowloss[r];
    sh[threadIdx.x] = s;
    __syncthreads();
    for (int o = 128; o; o >>= 1) {
        if (threadIdx.x < o) sh[threadIdx.x] += sh[threadIdx.x + o];
        __syncthreads();
    }
    if (threadIdx.x == 0) out[0] = sh[0] / (float)BATCH;
}

// ---------------------------------------------------------------------------
extern "C" void kernel_launch(void* const* d_in, const int* in_sizes, int n_in,
                              void* d_out, int out_size) {
    (void)in_sizes; (void)n_in; (void)out_size;
    const float* emb = (const float*)d_in[0];
    const float* wgt = (const float*)d_in[1];
    const void*  lbl = d_in[2];
    float* out       = (float*)d_out;

    cudaFuncSetAttribute(gemm_mma_kernel,
                         cudaFuncAttributeMaxDynamicSharedMemorySize, SM_TOTAL);

    detect_kernel<<<1, 512>>>(lbl);

    int totalRows = BATCH + NCLS_PAD;
    prep_kernel<<<(totalRows + 7) / 8, 256>>>(emb, wgt);

    dim3 grid(NCHUNK, BATCH / BM);
    gemm_mma_kernel<<<grid, 256, SM_TOTAL>>>();

    target_kernel<<<BATCH / 8, 256>>>(emb, wgt, lbl);
    lse_kernel<<<BATCH / 8, 256>>>();
    final_kernel<<<1, 256>>>(out);
}

// round 8
// speedup vs baseline: 6.8307x; 1.4014x over previous
#include <cuda_runtime.h>
#include <cuda_bf16.h>
#include <math.h>
#include <stdint.h>

#define BATCH    1024
#define DIM      512
#define NCLS     100000
#define NCLS_PAD 100096              // 782 * 128
#define SCALE    64.0f
#define MARGIN   0.5f
#define PI_F     3.14159265358979323846f

#define BM  128
#define BN  128
#define KT  32                        // K per pipeline stage
#define NSTAGE (DIM / KT)             // 16
#define NPIPE  4                      // pipeline depth (SMEM buffers)
#define NCHUNK (NCLS_PAD / BN)        // 782

#define STAGE_BYTES 16384             // A 8KB + B 8KB
#define SM_TOTAL (NPIPE * STAGE_BYTES)   // 65536

// ---------------- device scratch (no allocation allowed) -------------------
__device__ __nv_bfloat16 g_ebf[BATCH * DIM];       // normalized embeddings
__device__ __nv_bfloat16 g_wbf[NCLS_PAD * DIM];    // normalized weights (padded zero)
__device__ float g_inv_e[BATCH];
__device__ float g_inv_w[NCLS];
__device__ float g_pmax[BATCH * NCHUNK];
__device__ float g_psum[BATCH * NCHUNK];
__device__ float g_told[BATCH];
__device__ float g_tnew[BATCH];
__device__ float g_rowloss[BATCH];
__device__ int   g_lbl64;

// ---------------- PTX helpers (compute_103-safe: sm_80-era ops) -------------
__device__ __forceinline__ uint32_t smem_u32(const void* p) {
    uint32_t a;
    asm("{ .reg .u64 t; cvta.to.shared.u64 t, %1; cvt.u32.u64 %0, t; }" : "=r"(a) : "l"(p));
    return a;
}

__device__ __forceinline__ void cp_async16(uint32_t dst, const void* src) {
    asm volatile("cp.async.cg.shared.global [%0], [%1], 16;" :: "r"(dst), "l"(src));
}
#define CP_COMMIT() asm volatile("cp.async.commit_group;" ::: "memory")
#define CP_WAIT(n)  asm volatile("cp.async.wait_group %0;" :: "n"(n) : "memory")

__device__ __forceinline__ void ldsm_x4(uint32_t& r0, uint32_t& r1,
                                        uint32_t& r2, uint32_t& r3, uint32_t addr) {
    asm volatile("ldmatrix.sync.aligned.m8n8.x4.shared.b16 {%0,%1,%2,%3}, [%4];"
                 : "=r"(r0), "=r"(r1), "=r"(r2), "=r"(r3) : "r"(addr));
}

__device__ __forceinline__ void mma_bf16(float* c,
                                         uint32_t a0, uint32_t a1, uint32_t a2, uint32_t a3,
                                         uint32_t b0, uint32_t b1) {
    asm volatile(
        "mma.sync.aligned.m16n8k16.row.col.f32.bf16.bf16.f32 "
        "{%0,%1,%2,%3}, {%4,%5,%6,%7}, {%8,%9}, {%0,%1,%2,%3};"
        : "+f"(c[0]), "+f"(c[1]), "+f"(c[2]), "+f"(c[3])
        : "r"(a0), "r"(a1), "r"(a2), "r"(a3), "r"(b0), "r"(b1));
}

// SMEM swizzle for 64B rows of 4x16B chunks: chunk' = chunk ^ ((row>>1)&3).
// ldmatrix 8-row groups then hit 8 distinct bank-word positions (conflict-free),
// and every cp.async destination stays 16B-aligned.
__device__ __forceinline__ uint32_t sw_off(int row, int chunk) {
    return (uint32_t)(row * 64 + ((chunk ^ ((row >> 1) & 3)) << 4));
}

// ---------------------------------------------------------------------------
// Kernel 0: detect label dtype (reads exactly first 4KB; safe for i32/i64).
// ---------------------------------------------------------------------------
__global__ void detect_kernel(const void* __restrict__ lbl) {
    __shared__ int ok;
    if (threadIdx.x == 0) ok = 1;
    __syncthreads();
    long long v = ((const long long*)lbl)[threadIdx.x];   // 512 threads
    if (v < 0 || v >= (long long)NCLS) atomicAnd(&ok, 0);
    __syncthreads();
    if (threadIdx.x == 0) g_lbl64 = ok;
}

// ---------------------------------------------------------------------------
// Kernel 1: fused norm + bf16 convert. One warp per row.
// ---------------------------------------------------------------------------
__global__ void prep_kernel(const float* __restrict__ emb,
                            const float* __restrict__ wgt) {
    int row  = blockIdx.x * 8 + (threadIdx.x >> 5);
    int lane = threadIdx.x & 31;

    const float* src;
    __nv_bfloat16* dstRow;
    float* invDst;
    if (row < BATCH) {
        src = emb + (size_t)row * DIM;
        dstRow = &g_ebf[(size_t)row * DIM];
        invDst = &g_inv_e[row];
    } else {
        int r = row - BATCH;
        if (r >= NCLS_PAD) return;
        dstRow = &g_wbf[(size_t)r * DIM];
        if (r >= NCLS) {   // pad rows: zero
            uint2 z = make_uint2(0u, 0u);
#pragma unroll
            for (int i = 0; i < 4; i++) ((uint2*)dstRow)[lane + i * 32] = z;
            return;
        }
        src = wgt + (size_t)r * DIM;
        invDst = &g_inv_w[r];
    }

    const float4* p = (const float4*)src;
    float4 v[4];
    float s = 0.f;
#pragma unroll
    for (int i = 0; i < 4; i++) {
        v[i] = p[lane + i * 32];
        s = fmaf(v[i].x, v[i].x, s);
        s = fmaf(v[i].y, v[i].y, s);
        s = fmaf(v[i].z, v[i].z, s);
        s = fmaf(v[i].w, v[i].w, s);
    }
#pragma unroll
    for (int o = 16; o; o >>= 1) s += __shfl_xor_sync(0xFFFFFFFFu, s, o);
    float inv = rsqrtf(s);
    if (lane == 0) *invDst = inv;

#pragma unroll
    for (int i = 0; i < 4; i++) {
        __nv_bfloat162 lo = __floats2bfloat162_rn(v[i].x * inv, v[i].y * inv);
        __nv_bfloat162 hi = __floats2bfloat162_rn(v[i].z * inv, v[i].w * inv);
        uint2 pk;
        pk.x = *(uint32_t*)&lo;
        pk.y = *(uint32_t*)&hi;
        ((uint2*)dstRow)[lane + i * 32] = pk;
    }
}

// ---------------------------------------------------------------------------
// Kernel 2: bf16 mma.sync GEMM 128x128x512, cp.async 4-stage pipeline (KT=32),
// + per-chunk online-softmax partials.
// 8 warps (2 m x 4 n), warp tile 64x32, m16n8k16 fragments.
// ---------------------------------------------------------------------------
__device__ __forceinline__ void issue_stage(uint32_t smem_base, int sbuf,
                                            int rowBase, int colBase, int kBase, int tid) {
    const uint32_t aBase = smem_base + sbuf * STAGE_BYTES;
    const uint32_t bBase = aBase + 8192;
#pragma unroll
    for (int i = 0; i < 2; i++) {
        int idx = tid + i * 256;          // 0..511
        int r = idx >> 2;                  // 0..127
        int c = idx & 3;                   // 16B chunk within 64B row
        uint32_t off = sw_off(r, c);
        cp_async16(aBase + off, &g_ebf[(size_t)(rowBase + r) * DIM + kBase + c * 8]);
        cp_async16(bBase + off, &g_wbf[(size_t)(colBase + r) * DIM + kBase + c * 8]);
    }
}

__global__ __launch_bounds__(256, 2)
void gemm_mma_kernel() {
    extern __shared__ __align__(16) char smem[];
    const uint32_t smem_base = smem_u32(smem);
    const int tid  = threadIdx.x;
    const int wid  = tid >> 5;
    const int lane = tid & 31;
    const int wr   = wid >> 2;           // 0..1  (m)
    const int wc   = wid & 3;            // 0..3  (n)
    const int chunk   = blockIdx.x;
    const int rowBase = blockIdx.y * BM;
    const int colBase = chunk * BN;

    // per-lane ldmatrix row components
    const int r_in = lane & 7;
    const int a_row_base = wr * 64 + ((lane >> 3) & 1) * 8 + r_in;
    const int a_chunk    = (lane >> 4);          // + ks*2
    const int b_row_base = wc * 32 + (lane >> 4) * 8 + r_in;
    const int b_chunk    = ((lane >> 3) & 1);    // + ks*2

    float acc[4][4][4];
#pragma unroll
    for (int i = 0; i < 4; i++)
#pragma unroll
        for (int j = 0; j < 4; j++)
#pragma unroll
            for (int k = 0; k < 4; k++) acc[i][j][k] = 0.f;

    // prologue: stages 0..2 in flight
    issue_stage(smem_base, 0, rowBase, colBase, 0 * KT, tid); CP_COMMIT();
    issue_stage(smem_base, 1, rowBase, colBase, 1 * KT, tid); CP_COMMIT();
    issue_stage(smem_base, 2, rowBase, colBase, 2 * KT, tid); CP_COMMIT();

#pragma unroll
    for (int kt = 0; kt < NSTAGE; kt++) {
        CP_WAIT(2);                      // stage kt resident; kt+1, kt+2 in flight
        __syncthreads();

        const int sbuf = kt & 3;
        const uint32_t aBase = smem_base + sbuf * STAGE_BYTES;
        const uint32_t bBase = aBase + 8192;
#pragma unroll
        for (int ks = 0; ks < 2; ks++) {
            uint32_t af[4][4];
#pragma unroll
            for (int mi = 0; mi < 4; mi++) {
                int row = a_row_base + mi * 16;
                ldsm_x4(af[mi][0], af[mi][1], af[mi][2], af[mi][3],
                        aBase + sw_off(row, ks * 2 + a_chunk));
            }
            uint32_t bfr[4][2];
#pragma unroll
            for (int nb = 0; nb < 2; nb++) {
                int row = b_row_base + nb * 16;
                uint32_t r0, r1, r2, r3;
                ldsm_x4(r0, r1, r2, r3, bBase + sw_off(row, ks * 2 + b_chunk));
                bfr[nb * 2 + 0][0] = r0; bfr[nb * 2 + 0][1] = r1;
                bfr[nb * 2 + 1][0] = r2; bfr[nb * 2 + 1][1] = r3;
            }
#pragma unroll
            for (int mi = 0; mi < 4; mi++)
#pragma unroll
                for (int ni = 0; ni < 4; ni++)
                    mma_bf16(acc[mi][ni], af[mi][0], af[mi][1], af[mi][2], af[mi][3],
                             bfr[ni][0], bfr[ni][1]);
        }

        // refill buffer consumed at iteration kt-1 (all warps past the sync above)
        if (kt + 3 < NSTAGE)
            issue_stage(smem_base, (kt + 3) & 3, rowBase, colBase, (kt + 3) * KT, tid);
        CP_COMMIT();
    }
    __syncthreads();   // before SMEM reuse by the reduction

    // ---- epilogue: clip*64, per-row (max, sumexp) over this 128-col chunk --
    const int gid = lane >> 2;
    const int tg  = lane & 3;
    float2* red = (float2*)smem;            // [128][4]

#pragma unroll
    for (int mi = 0; mi < 4; mi++) {
#pragma unroll
        for (int h = 0; h < 2; h++) {
            const int rloc = wr * 64 + mi * 16 + h * 8 + gid;
            float vv[8];
            bool  okk[8];
            float lm = -1e30f;
#pragma unroll
            for (int ni = 0; ni < 4; ni++) {
#pragma unroll
                for (int c = 0; c < 2; c++) {
                    int n = wc * 32 + ni * 8 + tg * 2 + c;
                    float v = acc[mi][ni][h * 2 + c];
                    v = fminf(1.f, fmaxf(-1.f, v)) * SCALE;
                    bool ok = (colBase + n) < NCLS;
                    vv[ni * 2 + c] = v;
                    okk[ni * 2 + c] = ok;
                    if (ok) lm = fmaxf(lm, v);
                }
            }
            float ls = 0.f;
#pragma unroll
            for (int j = 0; j < 8; j++)
                if (okk[j]) ls += __expf(vv[j] - lm);
            // merge across the 4 tg lanes (quad)
#pragma unroll
            for (int o = 1; o <= 2; o <<= 1) {
                float om = __shfl_xor_sync(0xFFFFFFFFu, lm, o);
                float os = __shfl_xor_sync(0xFFFFFFFFu, ls, o);
                float mn = fmaxf(lm, om);
                ls = ls * __expf(lm - mn) + os * __expf(om - mn);
                lm = mn;
            }
            if (tg == 0) red[rloc * 4 + wc] = make_float2(lm, ls);
        }
    }
    __syncthreads();

    if (tid < BM) {
        float m = -1e30f, s = 0.f;
#pragma unroll
        for (int w = 0; w < 4; w++) {
            float2 p = red[tid * 4 + w];
            float mn = fmaxf(m, p.x);
            s = s * __expf(m - mn) + p.y * __expf(p.x - mn);
            m = mn;
        }
        g_pmax[(size_t)(rowBase + tid) * NCHUNK + chunk] = m;
        g_psum[(size_t)(rowBase + tid) * NCHUNK + chunk] = s;
    }
}

// ---------------------------------------------------------------------------
// Kernel 3: per-row target logit (fp32-exact). One warp per row.
// ---------------------------------------------------------------------------
__global__ void target_kernel(const float* __restrict__ emb,
                              const float* __restrict__ wgt,
                              const void* __restrict__ lbl) {
    int row  = blockIdx.x * 8 + (threadIdx.x >> 5);
    int lane = threadIdx.x & 31;
    if (row >= BATCH) return;

    long long lab = g_lbl64 ? ((const long long*)lbl)[row]
                            : (long long)((const int*)lbl)[row];

    const float4* e4 = (const float4*)(emb + (size_t)row * DIM);
    const float4* w4 = (const float4*)(wgt + (size_t)lab * DIM);
    float s = 0.f;
#pragma unroll
    for (int i = 0; i < 4; i++) {
        float4 a = e4[lane + i * 32];
        float4 b = w4[lane + i * 32];
        s = fmaf(a.x, b.x, s);
        s = fmaf(a.y, b.y, s);
        s = fmaf(a.z, b.z, s);
        s = fmaf(a.w, b.w, s);
    }
#pragma unroll
    for (int o = 16; o; o >>= 1) s += __shfl_xor_sync(0xFFFFFFFFu, s, o);

    if (lane == 0) {
        float t = s * g_inv_e[row] * g_inv_w[lab];
        t = fminf(1.f, fmaxf(-1.f, t));
        float th = acosf(t);
        float tn = cosf(fminf(th + MARGIN, PI_F));
        g_told[row] = t  * SCALE;
        g_tnew[row] = tn * SCALE;
    }
}

// ---------------------------------------------------------------------------
// Kernel 4: per-row LSE merge over NCHUNK partials + target substitution.
// ---------------------------------------------------------------------------
__global__ void lse_kernel() {
    int row  = blockIdx.x * 8 + (threadIdx.x >> 5);
    int lane = threadIdx.x & 31;
    if (row >= BATCH) return;

    float m = -1e30f, s = 0.f;
    const float* pm_base = &g_pmax[(size_t)row * NCHUNK];
    const float* ps_base = &g_psum[(size_t)row * NCHUNK];
    for (int ch = lane; ch < NCHUNK; ch += 32) {
        float pm = pm_base[ch];
        float ps = ps_base[ch];
        float mn = fmaxf(m, pm);
        s = s * __expf(m - mn) + ps * __expf(pm - mn);
        m = mn;
    }
#pragma unroll
    for (int o = 16; o; o >>= 1) {
        float om = __shfl_xor_sync(0xFFFFFFFFu, m, o);
        float os = __shfl_xor_sync(0xFFFFFFFFu, s, o);
        float mn = fmaxf(m, om);
        s = s * __expf(m - mn) + os * __expf(om - mn);
        m = mn;
    }
    if (lane == 0) {
        float tn = g_tnew[row];
        float to = g_told[row];
        float s2 = s + __expf(tn - m) - __expf(to - m);
        s2 = fmaxf(s2, 1e-30f);
        g_rowloss[row] = m + logf(s2) - tn;
    }
}

// ---------------------------------------------------------------------------
// Kernel 5: mean over rows -> d_out[0]
// ---------------------------------------------------------------------------
__global__ void final_kernel(float* __restrict__ out) {
    __shared__ float sh[256];
    float s = 0.f;
    for (int r = threadIdx.x; r < BATCH; r += 256) s += g_rowloss[r];
    sh[threadIdx.x] = s;
    __syncthreads();
    for (int o = 128; o; o >>= 1) {
        if (threadIdx.x < o) sh[threadIdx.x] += sh[threadIdx.x + o];
        __syncthreads();
    }
    if (threadIdx.x == 0) out[0] = sh[0] / (float)BATCH;
}

// ---------------------------------------------------------------------------
extern "C" void kernel_launch(void* const* d_in, const int* in_sizes, int n_in,
                              void* d_out, int out_size) {
    (void)in_sizes; (void)n_in; (void)out_size;
    const float* emb = (const float*)d_in[0];
    const float* wgt = (const float*)d_in[1];
    const void*  lbl = d_in[2];
    float* out       = (float*)d_out;

    cudaFuncSetAttribute(gemm_mma_kernel,
                         cudaFuncAttributeMaxDynamicSharedMemorySize, SM_TOTAL);

    detect_kernel<<<1, 512>>>(lbl);

    int totalRows = BATCH + NCLS_PAD;
    prep_kernel<<<(totalRows + 7) / 8, 256>>>(emb, wgt);

    dim3 grid(NCHUNK, BATCH / BM);
    gemm_mma_kernel<<<grid, 256, SM_TOTAL>>>();

    target_kernel<<<BATCH / 8, 256>>>(emb, wgt, lbl);
    lse_kernel<<<BATCH / 8, 256>>>();
    final_kernel<<<1, 256>>>(out);
}

// round 9
// speedup vs baseline: 6.9557x; 1.0183x over previous
#include <cuda_runtime.h>
#include <cuda_bf16.h>
#include <math.h>
#include <stdint.h>

#define BATCH    1024
#define DIM      512
#define NCLS     100000
#define NCLS_PAD 100096              // 782 * 128
#define SCALE    64.0f
#define MARGIN   0.5f
#define PI_F     3.14159265358979323846f

#define BM  128
#define BN  128
#define KT  32                        // K per pipeline stage
#define NSTAGE (DIM / KT)             // 16
#define NPIPE  4                      // pipeline depth (SMEM buffers)
#define NCHUNK (NCLS_PAD / BN)        // 782

#define STAGE_BYTES 16384             // A 8KB + B 8KB
#define SM_TOTAL (NPIPE * STAGE_BYTES)   // 65536

// ---------------- device scratch (no allocation allowed) -------------------
__device__ __nv_bfloat16 g_ebf[BATCH * DIM];       // normalized embeddings
__device__ __nv_bfloat16 g_wbf[NCLS_PAD * DIM];    // normalized weights (padded zero)
__device__ float g_inv_e[BATCH];
__device__ float g_inv_w[NCLS];
__device__ float g_pmax[BATCH * NCHUNK];
__device__ float g_psum[BATCH * NCHUNK];
__device__ float g_told[BATCH];
__device__ float g_tnew[BATCH];
__device__ float g_rowloss[BATCH];
__device__ int   g_lbl64;

// ---------------- PTX helpers (compute_103-safe: sm_80-era ops) -------------
__device__ __forceinline__ uint32_t smem_u32(const void* p) {
    uint32_t a;
    asm("{ .reg .u64 t; cvta.to.shared.u64 t, %1; cvt.u32.u64 %0, t; }" : "=r"(a) : "l"(p));
    return a;
}

__device__ __forceinline__ void cp_async16(uint32_t dst, const void* src) {
    asm volatile("cp.async.cg.shared.global [%0], [%1], 16;" :: "r"(dst), "l"(src));
}
#define CP_COMMIT() asm volatile("cp.async.commit_group;" ::: "memory")
#define CP_WAIT(n)  asm volatile("cp.async.wait_group %0;" :: "n"(n) : "memory")

__device__ __forceinline__ void ldsm_x4(uint32_t& r0, uint32_t& r1,
                                        uint32_t& r2, uint32_t& r3, uint32_t addr) {
    asm volatile("ldmatrix.sync.aligned.m8n8.x4.shared.b16 {%0,%1,%2,%3}, [%4];"
                 : "=r"(r0), "=r"(r1), "=r"(r2), "=r"(r3) : "r"(addr));
}

__device__ __forceinline__ void mma_bf16(float* c,
                                         uint32_t a0, uint32_t a1, uint32_t a2, uint32_t a3,
                                         uint32_t b0, uint32_t b1) {
    asm volatile(
        "mma.sync.aligned.m16n8k16.row.col.f32.bf16.bf16.f32 "
        "{%0,%1,%2,%3}, {%4,%5,%6,%7}, {%8,%9}, {%0,%1,%2,%3};"
        : "+f"(c[0]), "+f"(c[1]), "+f"(c[2]), "+f"(c[3])
        : "r"(a0), "r"(a1), "r"(a2), "r"(a3), "r"(b0), "r"(b1));
}

// SMEM swizzle for 64B rows of 4x16B chunks: chunk' = chunk ^ ((row>>1)&3).
// ldmatrix 8-row groups then hit 8 distinct bank-word positions (conflict-free),
// and every cp.async destination stays 16B-aligned.
__device__ __forceinline__ uint32_t sw_off(int row, int chunk) {
    return (uint32_t)(row * 64 + ((chunk ^ ((row >> 1) & 3)) << 4));
}

// ---------------------------------------------------------------------------
// Kernel 0: detect label dtype (reads exactly first 4KB; safe for i32/i64).
// ---------------------------------------------------------------------------
__global__ void detect_kernel(const void* __restrict__ lbl) {
    __shared__ int ok;
    if (threadIdx.x == 0) ok = 1;
    __syncthreads();
    long long v = ((const long long*)lbl)[threadIdx.x];   // 512 threads
    if (v < 0 || v >= (long long)NCLS) atomicAnd(&ok, 0);
    __syncthreads();
    if (threadIdx.x == 0) g_lbl64 = ok;
}

// ---------------------------------------------------------------------------
// Kernel 1: fused norm + bf16 convert. One warp per row.
// ---------------------------------------------------------------------------
__global__ void prep_kernel(const float* __restrict__ emb,
                            const float* __restrict__ wgt) {
    int row  = blockIdx.x * 8 + (threadIdx.x >> 5);
    int lane = threadIdx.x & 31;

    const float* src;
    __nv_bfloat16* dstRow;
    float* invDst;
    if (row < BATCH) {
        src = emb + (size_t)row * DIM;
        dstRow = &g_ebf[(size_t)row * DIM];
        invDst = &g_inv_e[row];
    } else {
        int r = row - BATCH;
        if (r >= NCLS_PAD) return;
        dstRow = &g_wbf[(size_t)r * DIM];
        if (r >= NCLS) {   // pad rows: zero
            uint2 z = make_uint2(0u, 0u);
#pragma unroll
            for (int i = 0; i < 4; i++) ((uint2*)dstRow)[lane + i * 32] = z;
            return;
        }
        src = wgt + (size_t)r * DIM;
        invDst = &g_inv_w[r];
    }

    const float4* p = (const float4*)src;
    float4 v[4];
    float s = 0.f;
#pragma unroll
    for (int i = 0; i < 4; i++) {
        v[i] = p[lane + i * 32];
        s = fmaf(v[i].x, v[i].x, s);
        s = fmaf(v[i].y, v[i].y, s);
        s = fmaf(v[i].z, v[i].z, s);
        s = fmaf(v[i].w, v[i].w, s);
    }
#pragma unroll
    for (int o = 16; o; o >>= 1) s += __shfl_xor_sync(0xFFFFFFFFu, s, o);
    float inv = rsqrtf(s);
    if (lane == 0) *invDst = inv;

#pragma unroll
    for (int i = 0; i < 4; i++) {
        __nv_bfloat162 lo = __floats2bfloat162_rn(v[i].x * inv, v[i].y * inv);
        __nv_bfloat162 hi = __floats2bfloat162_rn(v[i].z * inv, v[i].w * inv);
        uint2 pk;
        pk.x = *(uint32_t*)&lo;
        pk.y = *(uint32_t*)&hi;
        ((uint2*)dstRow)[lane + i * 32] = pk;
    }
}

// ---------------------------------------------------------------------------
// Kernel 2: bf16 mma.sync GEMM 128x128x512, cp.async 4-stage pipeline (KT=32),
// + per-chunk online-softmax partials.
// 8 warps (2 m x 4 n), warp tile 64x32, m16n8k16 fragments.
// Grid: x = row-block (8), y = chunk (782) -> consecutive CTA ids share one
// chunk's B tile, keeping it L2-resident (B read from DRAM once, not 8x).
// ---------------------------------------------------------------------------
__device__ __forceinline__ void issue_stage(uint32_t smem_base, int sbuf,
                                            int rowBase, int colBase, int kBase, int tid) {
    const uint32_t aBase = smem_base + sbuf * STAGE_BYTES;
    const uint32_t bBase = aBase + 8192;
#pragma unroll
    for (int i = 0; i < 2; i++) {
        int idx = tid + i * 256;          // 0..511
        int r = idx >> 2;                  // 0..127
        int c = idx & 3;                   // 16B chunk within 64B row
        uint32_t off = sw_off(r, c);
        cp_async16(aBase + off, &g_ebf[(size_t)(rowBase + r) * DIM + kBase + c * 8]);
        cp_async16(bBase + off, &g_wbf[(size_t)(colBase + r) * DIM + kBase + c * 8]);
    }
}

__global__ __launch_bounds__(256, 2)
void gemm_mma_kernel() {
    extern __shared__ __align__(16) char smem[];
    const uint32_t smem_base = smem_u32(smem);
    const int tid  = threadIdx.x;
    const int wid  = tid >> 5;
    const int lane = tid & 31;
    const int wr   = wid >> 2;           // 0..1  (m)
    const int wc   = wid & 3;            // 0..3  (n)
    const int chunk   = blockIdx.y;      // <-- swapped: chunk on y
    const int rowBase = blockIdx.x * BM; // <-- row-block on x (fast index)
    const int colBase = chunk * BN;

    // per-lane ldmatrix row components
    const int r_in = lane & 7;
    const int a_row_base = wr * 64 + ((lane >> 3) & 1) * 8 + r_in;
    const int a_chunk    = (lane >> 4);          // + ks*2
    const int b_row_base = wc * 32 + (lane >> 4) * 8 + r_in;
    const int b_chunk    = ((lane >> 3) & 1);    // + ks*2

    float acc[4][4][4];
#pragma unroll
    for (int i = 0; i < 4; i++)
#pragma unroll
        for (int j = 0; j < 4; j++)
#pragma unroll
            for (int k = 0; k < 4; k++) acc[i][j][k] = 0.f;

    // prologue: stages 0..2 in flight
    issue_stage(smem_base, 0, rowBase, colBase, 0 * KT, tid); CP_COMMIT();
    issue_stage(smem_base, 1, rowBase, colBase, 1 * KT, tid); CP_COMMIT();
    issue_stage(smem_base, 2, rowBase, colBase, 2 * KT, tid); CP_COMMIT();

#pragma unroll
    for (int kt = 0; kt < NSTAGE; kt++) {
        CP_WAIT(2);                      // stage kt resident; kt+1, kt+2 in flight
        __syncthreads();

        const int sbuf = kt & 3;
        const uint32_t aBase = smem_base + sbuf * STAGE_BYTES;
        const uint32_t bBase = aBase + 8192;
#pragma unroll
        for (int ks = 0; ks < 2; ks++) {
            uint32_t af[4][4];
#pragma unroll
            for (int mi = 0; mi < 4; mi++) {
                int row = a_row_base + mi * 16;
                ldsm_x4(af[mi][0], af[mi][1], af[mi][2], af[mi][3],
                        aBase + sw_off(row, ks * 2 + a_chunk));
            }
            uint32_t bfr[4][2];
#pragma unroll
            for (int nb = 0; nb < 2; nb++) {
                int row = b_row_base + nb * 16;
                uint32_t r0, r1, r2, r3;
                ldsm_x4(r0, r1, r2, r3, bBase + sw_off(row, ks * 2 + b_chunk));
                bfr[nb * 2 + 0][0] = r0; bfr[nb * 2 + 0][1] = r1;
                bfr[nb * 2 + 1][0] = r2; bfr[nb * 2 + 1][1] = r3;
            }
#pragma unroll
            for (int mi = 0; mi < 4; mi++)
#pragma unroll
                for (int ni = 0; ni < 4; ni++)
                    mma_bf16(acc[mi][ni], af[mi][0], af[mi][1], af[mi][2], af[mi][3],
                             bfr[ni][0], bfr[ni][1]);
        }

        // refill buffer consumed at iteration kt-1 (all warps past the sync above)
        if (kt + 3 < NSTAGE)
            issue_stage(smem_base, (kt + 3) & 3, rowBase, colBase, (kt + 3) * KT, tid);
        CP_COMMIT();
    }
    __syncthreads();   // before SMEM reuse by the reduction

    // ---- epilogue: clip*64, per-row (max, sumexp) over this 128-col chunk --
    const int gid = lane >> 2;
    const int tg  = lane & 3;
    float2* red = (float2*)smem;            // [128][4]

#pragma unroll
    for (int mi = 0; mi < 4; mi++) {
#pragma unroll
        for (int h = 0; h < 2; h++) {
            const int rloc = wr * 64 + mi * 16 + h * 8 + gid;
            float vv[8];
            bool  okk[8];
            float lm = -1e30f;
#pragma unroll
            for (int ni = 0; ni < 4; ni++) {
#pragma unroll
                for (int c = 0; c < 2; c++) {
                    int n = wc * 32 + ni * 8 + tg * 2 + c;
                    float v = acc[mi][ni][h * 2 + c];
                    v = fminf(1.f, fmaxf(-1.f, v)) * SCALE;
                    bool ok = (colBase + n) < NCLS;
                    vv[ni * 2 + c] = v;
                    okk[ni * 2 + c] = ok;
                    if (ok) lm = fmaxf(lm, v);
                }
            }
            float ls = 0.f;
#pragma unroll
            for (int j = 0; j < 8; j++)
                if (okk[j]) ls += __expf(vv[j] - lm);
            // merge across the 4 tg lanes (quad)
#pragma unroll
            for (int o = 1; o <= 2; o <<= 1) {
                float om = __shfl_xor_sync(0xFFFFFFFFu, lm, o);
                float os = __shfl_xor_sync(0xFFFFFFFFu, ls, o);
                float mn = fmaxf(lm, om);
                ls = ls * __expf(lm - mn) + os * __expf(om - mn);
                lm = mn;
            }
            if (tg == 0) red[rloc * 4 + wc] = make_float2(lm, ls);
        }
    }
    __syncthreads();

    if (tid < BM) {
        float m = -1e30f, s = 0.f;
#pragma unroll
        for (int w = 0; w < 4; w++) {
            float2 p = red[tid * 4 + w];
            float mn = fmaxf(m, p.x);
            s = s * __expf(m - mn) + p.y * __expf(p.x - mn);
            m = mn;
        }
        g_pmax[(size_t)(rowBase + tid) * NCHUNK + chunk] = m;
        g_psum[(size_t)(rowBase + tid) * NCHUNK + chunk] = s;
    }
}

// ---------------------------------------------------------------------------
// Kernel 3: per-row target logit (fp32-exact). One warp per row.
// ---------------------------------------------------------------------------
__global__ void target_kernel(const float* __restrict__ emb,
                              const float* __restrict__ wgt,
                              const void* __restrict__ lbl) {
    int row  = blockIdx.x * 8 + (threadIdx.x >> 5);
    int lane = threadIdx.x & 31;
    if (row >= BATCH) return;

    long long lab = g_lbl64 ? ((const long long*)lbl)[row]
                            : (long long)((const int*)lbl)[row];

    const float4* e4 = (const float4*)(emb + (size_t)row * DIM);
    const float4* w4 = (const float4*)(wgt + (size_t)lab * DIM);
    float s = 0.f;
#pragma unroll
    for (int i = 0; i < 4; i++) {
        float4 a = e4[lane + i * 32];
        float4 b = w4[lane + i * 32];
        s = fmaf(a.x, b.x, s);
        s = fmaf(a.y, b.y, s);
        s = fmaf(a.z, b.z, s);
        s = fmaf(a.w, b.w, s);
    }
#pragma unroll
    for (int o = 16; o; o >>= 1) s += __shfl_xor_sync(0xFFFFFFFFu, s, o);

    if (lane == 0) {
        float t = s * g_inv_e[row] * g_inv_w[lab];
        t = fminf(1.f, fmaxf(-1.f, t));
        float th = acosf(t);
        float tn = cosf(fminf(th + MARGIN, PI_F));
        g_told[row] = t  * SCALE;
        g_tnew[row] = tn * SCALE;
    }
}

// ---------------------------------------------------------------------------
// Kernel 4: per-row LSE merge over NCHUNK partials + target substitution.
// ---------------------------------------------------------------------------
__global__ void lse_kernel() {
    int row  = blockIdx.x * 8 + (threadIdx.x >> 5);
    int lane = threadIdx.x & 31;
    if (row >= BATCH) return;

    float m = -1e30f, s = 0.f;
    const float* pm_base = &g_pmax[(size_t)row * NCHUNK];
    const float* ps_base = &g_psum[(size_t)row * NCHUNK];
    for (int ch = lane; ch < NCHUNK; ch += 32) {
        float pm = pm_base[ch];
        float ps = ps_base[ch];
        float mn = fmaxf(m, pm);
        s = s * __expf(m - mn) + ps * __expf(pm - mn);
        m = mn;
    }
#pragma unroll
    for (int o = 16; o; o >>= 1) {
        float om = __shfl_xor_sync(0xFFFFFFFFu, m, o);
        float os = __shfl_xor_sync(0xFFFFFFFFu, s, o);
        float mn = fmaxf(m, om);
        s = s * __expf(m - mn) + os * __expf(om - mn);
        m = mn;
    }
    if (lane == 0) {
        float tn = g_tnew[row];
        float to = g_told[row];
        float s2 = s + __expf(tn - m) - __expf(to - m);
        s2 = fmaxf(s2, 1e-30f);
        g_rowloss[row] = m + logf(s2) - tn;
    }
}

// ---------------------------------------------------------------------------
// Kernel 5: mean over rows -> d_out[0]
// ---------------------------------------------------------------------------
__global__ void final_kernel(float* __restrict__ out) {
    __shared__ float sh[256];
    float s = 0.f;
    for (int r = threadIdx.x; r < BATCH; r += 256) s += g_rowloss[r];
    sh[threadIdx.x] = s;
    __syncthreads();
    for (int o = 128; o; o >>= 1) {
        if (threadIdx.x < o) sh[threadIdx.x] += sh[threadIdx.x + o];
        __syncthreads();
    }
    if (threadIdx.x == 0) out[0] = sh[0] / (float)BATCH;
}

// ---------------------------------------------------------------------------
extern "C" void kernel_launch(void* const* d_in, const int* in_sizes, int n_in,
                              void* d_out, int out_size) {
    (void)in_sizes; (void)n_in; (void)out_size;
    const float* emb = (const float*)d_in[0];
    const float* wgt = (const float*)d_in[1];
    const void*  lbl = d_in[2];
    float* out       = (float*)d_out;

    cudaFuncSetAttribute(gemm_mma_kernel,
                         cudaFuncAttributeMaxDynamicSharedMemorySize, SM_TOTAL);

    detect_kernel<<<1, 512>>>(lbl);

    int totalRows = BATCH + NCLS_PAD;
    prep_kernel<<<(totalRows + 7) / 8, 256>>>(emb, wgt);

    dim3 grid(BATCH / BM, NCHUNK);   // x = row-block (fast), y = chunk
    gemm_mma_kernel<<<grid, 256, SM_TOTAL>>>();

    target_kernel<<<BATCH / 8, 256>>>(emb, wgt, lbl);
    lse_kernel<<<BATCH / 8, 256>>>();
    final_kernel<<<1, 256>>>(out);
}

// round 10
// speedup vs baseline: 6.9912x; 1.0051x over previous
#include <cuda_runtime.h>
#include <cuda_bf16.h>
#include <math.h>
#include <stdint.h>

#define BATCH    1024
#define DIM      512
#define NCLS     100000
#define NCLS_PAD 100096              // 782 * 128
#define SCALE    64.0f
#define MARGIN   0.5f
#define PI_F     3.14159265358979323846f

#define BM  128
#define BN  128
#define KT  32                        // K per pipeline stage
#define NSTAGE (DIM / KT)             // 16
#define NPIPE  4                      // pipeline depth (SMEM buffers)
#define NCHUNK (NCLS_PAD / BN)        // 782
#define LA  64                        // prep lookahead (chunks)

#define STAGE_BYTES 16384             // A 8KB + B 8KB
#define SM_TOTAL (NPIPE * STAGE_BYTES)   // 65536

// ---------------- device scratch (no allocation allowed) -------------------
__device__ __nv_bfloat16 g_ebf[BATCH * DIM];       // normalized embeddings
__device__ __nv_bfloat16 g_wbf[NCLS_PAD * DIM];    // normalized weights (padded zero)
__device__ float g_inv_e[BATCH];
__device__ float g_inv_w[NCLS];
__device__ float g_pmax[BATCH * NCHUNK];
__device__ float g_psum[BATCH * NCHUNK];
__device__ float g_rowloss[BATCH];
__device__ int   g_lbl64;
__device__ int   g_flag[NCHUNK];                   // per-chunk "W prepped" flag

// ---------------- PTX helpers (compute_103-safe: sm_80-era ops) -------------
__device__ __forceinline__ uint32_t smem_u32(const void* p) {
    uint32_t a;
    asm("{ .reg .u64 t; cvta.to.shared.u64 t, %1; cvt.u32.u64 %0, t; }" : "=r"(a) : "l"(p));
    return a;
}

__device__ __forceinline__ void cp_async16(uint32_t dst, const void* src) {
    asm volatile("cp.async.cg.shared.global [%0], [%1], 16;" :: "r"(dst), "l"(src));
}
#define CP_COMMIT() asm volatile("cp.async.commit_group;" ::: "memory")
#define CP_WAIT(n)  asm volatile("cp.async.wait_group %0;" :: "n"(n) : "memory")

__device__ __forceinline__ void ldsm_x4(uint32_t& r0, uint32_t& r1,
                                        uint32_t& r2, uint32_t& r3, uint32_t addr) {
    asm volatile("ldmatrix.sync.aligned.m8n8.x4.shared.b16 {%0,%1,%2,%3}, [%4];"
                 : "=r"(r0), "=r"(r1), "=r"(r2), "=r"(r3) : "r"(addr));
}

__device__ __forceinline__ void mma_bf16(float* c,
                                         uint32_t a0, uint32_t a1, uint32_t a2, uint32_t a3,
                                         uint32_t b0, uint32_t b1) {
    asm volatile(
        "mma.sync.aligned.m16n8k16.row.col.f32.bf16.bf16.f32 "
        "{%0,%1,%2,%3}, {%4,%5,%6,%7}, {%8,%9}, {%0,%1,%2,%3};"
        : "+f"(c[0]), "+f"(c[1]), "+f"(c[2]), "+f"(c[3])
        : "r"(a0), "r"(a1), "r"(a2), "r"(a3), "r"(b0), "r"(b1));
}

// SMEM swizzle for 64B rows of 4x16B chunks: chunk' = chunk ^ ((row>>1)&3).
__device__ __forceinline__ uint32_t sw_off(int row, int chunk) {
    return (uint32_t)(row * 64 + ((chunk ^ ((row >> 1) & 3)) << 4));
}

// ---------------------------------------------------------------------------
// normalize one f32 row -> bf16 row (warp-cooperative), returns inv-norm
// ---------------------------------------------------------------------------
__device__ __forceinline__ float norm_row_to_bf16(const float* __restrict__ src,
                                                  __nv_bfloat16* __restrict__ dst,
                                                  int lane) {
    const float4* p = (const float4*)src;
    float4 v[4];
    float s = 0.f;
#pragma unroll
    for (int i = 0; i < 4; i++) {
        v[i] = p[lane + i * 32];
        s = fmaf(v[i].x, v[i].x, s);
        s = fmaf(v[i].y, v[i].y, s);
        s = fmaf(v[i].z, v[i].z, s);
        s = fmaf(v[i].w, v[i].w, s);
    }
#pragma unroll
    for (int o = 16; o; o >>= 1) s += __shfl_xor_sync(0xFFFFFFFFu, s, o);
    float inv = rsqrtf(s);
#pragma unroll
    for (int i = 0; i < 4; i++) {
        __nv_bfloat162 lo = __floats2bfloat162_rn(v[i].x * inv, v[i].y * inv);
        __nv_bfloat162 hi = __floats2bfloat162_rn(v[i].z * inv, v[i].w * inv);
        uint2 pk;
        pk.x = *(uint32_t*)&lo;
        pk.y = *(uint32_t*)&hi;
        ((uint2*)dst)[lane + i * 32] = pk;
    }
    return inv;
}

// ---------------------------------------------------------------------------
// Kernel 0: detect label dtype + zero per-chunk flags (replay-deterministic).
// ---------------------------------------------------------------------------
__global__ void detect_kernel(const void* __restrict__ lbl) {
    __shared__ int ok;
    if (threadIdx.x == 0) ok = 1;
    __syncthreads();
    long long v = ((const long long*)lbl)[threadIdx.x];   // 512 threads, first 4KB
    if (v < 0 || v >= (long long)NCLS) atomicAnd(&ok, 0);
    for (int i = threadIdx.x; i < NCHUNK; i += 512) g_flag[i] = 0;
    __syncthreads();
    if (threadIdx.x == 0) g_lbl64 = ok;
}

// ---------------------------------------------------------------------------
// Kernel 1: initial prep — embeddings + first LA chunks of W. One warp/row.
// ---------------------------------------------------------------------------
__global__ void prep_kernel(const float* __restrict__ emb,
                            const float* __restrict__ wgt) {
    int row  = blockIdx.x * 8 + (threadIdx.x >> 5);
    int lane = threadIdx.x & 31;

    if (row < BATCH) {
        float inv = norm_row_to_bf16(emb + (size_t)row * DIM,
                                     &g_ebf[(size_t)row * DIM], lane);
        if (lane == 0) g_inv_e[row] = inv;
    } else {
        int r = row - BATCH;
        if (r >= LA * BN) return;       // only first LA chunks here (all < NCLS)
        float inv = norm_row_to_bf16(wgt + (size_t)r * DIM,
                                     &g_wbf[(size_t)r * DIM], lane);
        if (lane == 0) g_inv_w[r] = inv;
    }
}

// ---------------------------------------------------------------------------
// Kernel 2: bf16 mma.sync GEMM 128x128x512, cp.async 4-stage pipeline (KT=32),
// + distributed W-prep with LA-chunk lookahead + per-chunk softmax partials.
// Grid: x = row-block (8, fast), y = chunk (782).
// ---------------------------------------------------------------------------
__device__ __forceinline__ void prep_chunk(const float* __restrict__ wgt,
                                           int pchunk, int tid) {
    const int wid = tid >> 5, lane = tid & 31;
    const int base = pchunk * BN;
#pragma unroll 1
    for (int i = 0; i < 16; i++) {
        int r = base + wid * 16 + i;
        __nv_bfloat16* dst = &g_wbf[(size_t)r * DIM];
        if (r >= NCLS) {                 // pad rows: zero
            uint2 z = make_uint2(0u, 0u);
#pragma unroll
            for (int j = 0; j < 4; j++) ((uint2*)dst)[lane + j * 32] = z;
            continue;
        }
        float inv = norm_row_to_bf16(wgt + (size_t)r * DIM, dst, lane);
        if (lane == 0) g_inv_w[r] = inv;
    }
    __threadfence();                      // release all threads' writes
    __syncthreads();
    if (tid == 0) atomicExch(&g_flag[pchunk], 1);
}

__device__ __forceinline__ void issue_stage(uint32_t smem_base, int sbuf,
                                            int rowBase, int colBase, int kBase, int tid) {
    const uint32_t aBase = smem_base + sbuf * STAGE_BYTES;
    const uint32_t bBase = aBase + 8192;
#pragma unroll
    for (int i = 0; i < 2; i++) {
        int idx = tid + i * 256;          // 0..511
        int r = idx >> 2;                  // 0..127
        int c = idx & 3;                   // 16B chunk within 64B row
        uint32_t off = sw_off(r, c);
        cp_async16(aBase + off, &g_ebf[(size_t)(rowBase + r) * DIM + kBase + c * 8]);
        cp_async16(bBase + off, &g_wbf[(size_t)(colBase + r) * DIM + kBase + c * 8]);
    }
}

__global__ __launch_bounds__(256, 2)
void gemm_mma_kernel(const float* __restrict__ wgt) {
    extern __shared__ __align__(16) char smem[];
    const uint32_t smem_base = smem_u32(smem);
    const int tid  = threadIdx.x;
    const int wid  = tid >> 5;
    const int lane = tid & 31;
    const int wr   = wid >> 2;           // 0..1  (m)
    const int wc   = wid & 3;            // 0..3  (n)
    const int chunk   = blockIdx.y;
    const int rowBase = blockIdx.x * BM;
    const int colBase = chunk * BN;

    // ---- distributed W-prep: x==0 CTA preps chunk (chunk+LA) --------------
    if (blockIdx.x == 0 && chunk + LA < NCHUNK)
        prep_chunk(wgt, chunk + LA, tid);

    // ---- wait for this chunk's W tile (chunks < LA prepped by prep_kernel) -
    if (chunk >= LA) {
        if (tid == 0) {
            while (atomicOr(&g_flag[chunk], 0) == 0) __nanosleep(64);
            __threadfence();              // acquire
        }
        __syncthreads();
    }

    // per-lane ldmatrix row components
    const int r_in = lane & 7;
    const int a_row_base = wr * 64 + ((lane >> 3) & 1) * 8 + r_in;
    const int a_chunk    = (lane >> 4);          // + ks*2
    const int b_row_base = wc * 32 + (lane >> 4) * 8 + r_in;
    const int b_chunk    = ((lane >> 3) & 1);    // + ks*2

    float acc[4][4][4];
#pragma unroll
    for (int i = 0; i < 4; i++)
#pragma unroll
        for (int j = 0; j < 4; j++)
#pragma unroll
            for (int k = 0; k < 4; k++) acc[i][j][k] = 0.f;

    // prologue: stages 0..2 in flight
    issue_stage(smem_base, 0, rowBase, colBase, 0 * KT, tid); CP_COMMIT();
    issue_stage(smem_base, 1, rowBase, colBase, 1 * KT, tid); CP_COMMIT();
    issue_stage(smem_base, 2, rowBase, colBase, 2 * KT, tid); CP_COMMIT();

#pragma unroll
    for (int kt = 0; kt < NSTAGE; kt++) {
        CP_WAIT(2);                      // stage kt resident; kt+1, kt+2 in flight
        __syncthreads();

        const int sbuf = kt & 3;
        const uint32_t aBase = smem_base + sbuf * STAGE_BYTES;
        const uint32_t bBase = aBase + 8192;
#pragma unroll
        for (int ks = 0; ks < 2; ks++) {
            uint32_t af[4][4];
#pragma unroll
            for (int mi = 0; mi < 4; mi++) {
                int row = a_row_base + mi * 16;
                ldsm_x4(af[mi][0], af[mi][1], af[mi][2], af[mi][3],
                        aBase + sw_off(row, ks * 2 + a_chunk));
            }
            uint32_t bfr[4][2];
#pragma unroll
            for (int nb = 0; nb < 2; nb++) {
                int row = b_row_base + nb * 16;
                uint32_t r0, r1, r2, r3;
                ldsm_x4(r0, r1, r2, r3, bBase + sw_off(row, ks * 2 + b_chunk));
                bfr[nb * 2 + 0][0] = r0; bfr[nb * 2 + 0][1] = r1;
                bfr[nb * 2 + 1][0] = r2; bfr[nb * 2 + 1][1] = r3;
            }
#pragma unroll
            for (int mi = 0; mi < 4; mi++)
#pragma unroll
                for (int ni = 0; ni < 4; ni++)
                    mma_bf16(acc[mi][ni], af[mi][0], af[mi][1], af[mi][2], af[mi][3],
                             bfr[ni][0], bfr[ni][1]);
        }

        // refill buffer consumed at iteration kt-1
        if (kt + 3 < NSTAGE)
            issue_stage(smem_base, (kt + 3) & 3, rowBase, colBase, (kt + 3) * KT, tid);
        CP_COMMIT();
    }
    __syncthreads();   // before SMEM reuse by the reduction

    // ---- epilogue: clip*64, per-row (max, sumexp) over this 128-col chunk --
    const int gid = lane >> 2;
    const int tg  = lane & 3;
    float2* red = (float2*)smem;            // [128][4]

#pragma unroll
    for (int mi = 0; mi < 4; mi++) {
#pragma unroll
        for (int h = 0; h < 2; h++) {
            const int rloc = wr * 64 + mi * 16 + h * 8 + gid;
            float vv[8];
            bool  okk[8];
            float lm = -1e30f;
#pragma unroll
            for (int ni = 0; ni < 4; ni++) {
#pragma unroll
                for (int c = 0; c < 2; c++) {
                    int n = wc * 32 + ni * 8 + tg * 2 + c;
                    float v = acc[mi][ni][h * 2 + c];
                    v = fminf(1.f, fmaxf(-1.f, v)) * SCALE;
                    bool ok = (colBase + n) < NCLS;
                    vv[ni * 2 + c] = v;
                    okk[ni * 2 + c] = ok;
                    if (ok) lm = fmaxf(lm, v);
                }
            }
            float ls = 0.f;
#pragma unroll
            for (int j = 0; j < 8; j++)
                if (okk[j]) ls += __expf(vv[j] - lm);
#pragma unroll
            for (int o = 1; o <= 2; o <<= 1) {
                float om = __shfl_xor_sync(0xFFFFFFFFu, lm, o);
                float os = __shfl_xor_sync(0xFFFFFFFFu, ls, o);
                float mn = fmaxf(lm, om);
                ls = ls * __expf(lm - mn) + os * __expf(om - mn);
                lm = mn;
            }
            if (tg == 0) red[rloc * 4 + wc] = make_float2(lm, ls);
        }
    }
    __syncthreads();

    if (tid < BM) {
        float m = -1e30f, s = 0.f;
#pragma unroll
        for (int w = 0; w < 4; w++) {
            float2 p = red[tid * 4 + w];
            float mn = fmaxf(m, p.x);
            s = s * __expf(m - mn) + p.y * __expf(p.x - mn);
            m = mn;
        }
        g_pmax[(size_t)(rowBase + tid) * NCHUNK + chunk] = m;
        g_psum[(size_t)(rowBase + tid) * NCHUNK + chunk] = s;
    }
}

// ---------------------------------------------------------------------------
// Kernel 3: fused target + LSE. One warp per row.
//   t  = clip(dot(emb,W[lab]) * invE * invW);  tn = cos(min(acos(t)+M, pi))
//   lse over 782 chunk partials; row_loss = lse' - tn after substitution.
// ---------------------------------------------------------------------------
__global__ void tail_kernel(const float* __restrict__ emb,
                            const float* __restrict__ wgt,
                            const void* __restrict__ lbl) {
    int row  = blockIdx.x * 8 + (threadIdx.x >> 5);
    int lane = threadIdx.x & 31;
    if (row >= BATCH) return;

    long long lab = g_lbl64 ? ((const long long*)lbl)[row]
                            : (long long)((const int*)lbl)[row];

    // fp32-exact target dot
    const float4* e4 = (const float4*)(emb + (size_t)row * DIM);
    const float4* w4 = (const float4*)(wgt + (size_t)lab * DIM);
    float td = 0.f;
#pragma unroll
    for (int i = 0; i < 4; i++) {
        float4 a = e4[lane + i * 32];
        float4 b = w4[lane + i * 32];
        td = fmaf(a.x, b.x, td);
        td = fmaf(a.y, b.y, td);
        td = fmaf(a.z, b.z, td);
        td = fmaf(a.w, b.w, td);
    }
#pragma unroll
    for (int o = 16; o; o >>= 1) td += __shfl_xor_sync(0xFFFFFFFFu, td, o);

    // LSE merge over chunk partials
    float m = -1e30f, s = 0.f;
    const float* pm_base = &g_pmax[(size_t)row * NCHUNK];
    const float* ps_base = &g_psum[(size_t)row * NCHUNK];
    for (int ch = lane; ch < NCHUNK; ch += 32) {
        float pm = pm_base[ch];
        float ps = ps_base[ch];
        float mn = fmaxf(m, pm);
        s = s * __expf(m - mn) + ps * __expf(pm - mn);
        m = mn;
    }
#pragma unroll
    for (int o = 16; o; o >>= 1) {
        float om = __shfl_xor_sync(0xFFFFFFFFu, m, o);
        float os = __shfl_xor_sync(0xFFFFFFFFu, s, o);
        float mn = fmaxf(m, om);
        s = s * __expf(m - mn) + os * __expf(om - mn);
        m = mn;
    }

    if (lane == 0) {
        float t = td * g_inv_e[row] * g_inv_w[lab];
        t = fminf(1.f, fmaxf(-1.f, t));
        float th = acosf(t);
        float tn = cosf(fminf(th + MARGIN, PI_F)) * SCALE;
        float to = t * SCALE;
        float s2 = s + __expf(tn - m) - __expf(to - m);
        s2 = fmaxf(s2, 1e-30f);
        g_rowloss[row] = m + logf(s2) - tn;
    }
}

// ---------------------------------------------------------------------------
// Kernel 4: mean over rows -> d_out[0]
// ---------------------------------------------------------------------------
__global__ void final_kernel(float* __restrict__ out) {
    __shared__ float sh[256];
    float s = 0.f;
    for (int r = threadIdx.x; r < BATCH; r += 256) s += g_rowloss[r];
    sh[threadIdx.x] = s;
    __syncthreads();
    for (int o = 128; o; o >>= 1) {
        if (threadIdx.x < o) sh[threadIdx.x] += sh[threadIdx.x + o];
        __syncthreads();
    }
    if (threadIdx.x == 0) out[0] = sh[0] / (float)BATCH;
}

// ---------------------------------------------------------------------------
extern "C" void kernel_launch(void* const* d_in, const int* in_sizes, int n_in,
                              void* d_out, int out_size) {
    (void)in_sizes; (void)n_in; (void)out_size;
    const float* emb = (const float*)d_in[0];
    const float* wgt = (const float*)d_in[1];
    const void*  lbl = d_in[2];
    float* out       = (float*)d_out;

    cudaFuncSetAttribute(gemm_mma_kernel,
                         cudaFuncAttributeMaxDynamicSharedMemorySize, SM_TOTAL);

    detect_kernel<<<1, 512>>>(lbl);

    // initial prep: embeddings (1024 rows) + first LA chunks of W (8192 rows)
    int totalRows = BATCH + LA * BN;
    prep_kernel<<<(totalRows + 7) / 8, 256>>>(emb, wgt);

    dim3 grid(BATCH / BM, NCHUNK);   // x = row-block (fast), y = chunk
    gemm_mma_kernel<<<grid, 256, SM_TOTAL>>>(wgt);

    tail_kernel<<<BATCH / 8, 256>>>(emb, wgt, lbl);
    final_kernel<<<1, 256>>>(out);
}